// round 16
// baseline (speedup 1.0000x reference)
#include <cuda_runtime.h>
#include <stdint.h>

#define CIN    64
#define COUT   64
#define HW     16384
#define NGRP   16

__device__ __forceinline__ int dp4a_us(unsigned a, int b, int c) {
    int r;
    asm("dp4a.u32.s32 %0, %1, %2, %3;" : "=r"(r) : "r"(a), "r"(b), "r"(c));
    return r;
}

__device__ __forceinline__ unsigned pack4(int a, int b, int c, int d) {
    unsigned lo = __byte_perm((unsigned)a, (unsigned)b, 0x0040);
    unsigned hi = __byte_perm((unsigned)c, (unsigned)d, 0x0040);
    return __byte_perm(lo, hi, 0x5410);
}

__device__ __forceinline__ void acc8(int acc[4][2], const unsigned xw0,
                                     const unsigned xw1, const int4 w4) {
    acc[0][0] = dp4a_us(xw0, w4.x, acc[0][0]);
    acc[0][1] = dp4a_us(xw1, w4.x, acc[0][1]);
    acc[1][0] = dp4a_us(xw0, w4.y, acc[1][0]);
    acc[1][1] = dp4a_us(xw1, w4.y, acc[1][1]);
    acc[2][0] = dp4a_us(xw0, w4.z, acc[2][0]);
    acc[2][1] = dp4a_us(xw1, w4.z, acc[2][1]);
    acc[3][0] = dp4a_us(xw0, w4.w, acc[3][0]);
    acc[3][1] = dp4a_us(xw1, w4.w, acc[3][1]);
}

template<bool HASZP>
__device__ __forceinline__ void conv_body(const int2* __restrict__ xb,
                                          float2* __restrict__ o2,
                                          int out_base,
                                          const int* s_w,
                                          const float4* s_P)
{
    // load 64 channels x 2 positions; pack to u8x4 words per (group, pos)
    unsigned xw[NGRP][2];
#pragma unroll
    for (int g = 0; g < NGRP; g++) {
        int2 a0 = __ldg(xb + (g * 4 + 0) * (HW / 2));
        int2 a1 = __ldg(xb + (g * 4 + 1) * (HW / 2));
        int2 a2 = __ldg(xb + (g * 4 + 2) * (HW / 2));
        int2 a3 = __ldg(xb + (g * 4 + 3) * (HW / 2));
        xw[g][0] = pack4(a0.x, a1.x, a2.x, a3.x);
        xw[g][1] = pack4(a0.y, a1.y, a2.y, a3.y);
    }

    // per-position channel sums only needed when any wzp != 0
    float sxf0 = 0.0f, sxf1 = 0.0f;
    if (HASZP) {
        int sx0 = 0, sx1 = 0;
#pragma unroll
        for (int g = 0; g < NGRP; g++) {
            sx0 = dp4a_us(xw[g][0], 0x01010101, sx0);
            sx1 = dp4a_us(xw[g][1], 0x01010101, sx1);
        }
        sxf0 = (float)sx0;
        sxf1 = (float)sx1;
    }

    for (int q = 0; q < NGRP; q++) {      // 16 output-channel quads
        int acc[4][2] = {};
        // software-pipelined weight loads: two int4 buffers, no copies
        int4 wA = *(const int4*)(s_w + 0 * COUT + q * 4);
#pragma unroll
        for (int g = 0; g < NGRP; g += 2) {
            int4 wB = *(const int4*)(s_w + (g + 1) * COUT + q * 4);
            acc8(acc, xw[g][0], xw[g][1], wA);
            if (g + 2 < NGRP)
                wA = *(const int4*)(s_w + (g + 2) * COUT + q * 4);
            acc8(acc, xw[g + 1][0], xw[g + 1][1], wB);
        }
#pragma unroll
        for (int j = 0; j < 4; j++) {
            int o = q * 4 + j;
            float4 P = s_P[o];            // broadcast LDS.128: S, C0, C1
            float base0 = HASZP ? fmaf(P.z, sxf0, P.y) : P.y;
            float base1 = HASZP ? fmaf(P.z, sxf1, P.y) : P.y;
            float f0 = fmaf(P.x, (float)acc[j][0], base0);
            float f1 = fmaf(P.x, (float)acc[j][1], base1);
            float r0 = fminf(fmaxf(rintf(f0), 0.0f), 255.0f);
            float r1 = fminf(fmaxf(rintf(f1), 0.0f), 255.0f);
            o2[out_base + o * (HW / 2)] = make_float2(r0, r1);
        }
    }
}

__global__ __launch_bounds__(256, 3) void conv_fused(
    const int2*  __restrict__ x,
    float2*      __restrict__ out,
    const int4*  __restrict__ w,
    const float* __restrict__ wscale,
    const int*   __restrict__ wzp,
    const float* __restrict__ bias,
    const float* __restrict__ iscale,
    const float* __restrict__ oscale,
    const int*   __restrict__ izp_p,
    const int*   __restrict__ ozp_p)
{
    __shared__ int    s_w[NGRP * COUT];   // [group][o] packed s8 weights
    __shared__ float4 s_P[COUT];          // (S, C0, C1, 0) per output channel

    const int tid = threadIdx.x;
    int myzp = 0;

    // ---- inlined prep: threads 0..63 each build one output channel ----
    if (tid < COUT) {
        const int o = tid;
        int sum = 0;
#pragma unroll
        for (int g = 0; g < NGRP; g++) {
            int4 v = __ldg(w + o * NGRP + g);
            sum += v.x + v.y + v.z + v.w;
            s_w[g * COUT + o] = (int)pack4(v.x, v.y, v.z, v.w);
        }
        myzp = __ldg(wzp + o);
        float s   = iscale[0] * wscale[o] / oscale[0];
        float izp = (float)izp_p[0];
        float zw  = (float)myzp;
        // round(f)+ozp == round(f+ozp) for integer ozp -> fold ozp into C0
        float C0  = bias[o] / oscale[0]
                  + s * izp * (64.0f * zw - (float)sum)
                  + (float)ozp_p[0];
        s_P[o] = make_float4(s, C0, -s * zw, 0.0f);
    }
    // barrier + block-wide OR of "any weight zero-point nonzero"
    const int haszp = __syncthreads_or(myzp != 0);

    int gp = (blockIdx.x * 256 + tid) << 1;  // 2 consecutive w positions
    int b  = gp >> 14;                        // / HW
    int hw = gp & (HW - 1);

    const int2* xb = x + (b * (CIN * HW / 2) + (hw >> 1));
    const int out_base = b * COUT * (HW / 2) + (hw >> 1);   // float2 units

    if (haszp)
        conv_body<true>(xb, out, out_base, s_w, s_P);
    else
        conv_body<false>(xb, out, out_base, s_w, s_P);
}

extern "C" void kernel_launch(void* const* d_in, const int* in_sizes, int n_in,
                              void* d_out, int out_size) {
    // 0: x_quant (i32)  1: input_scale (f32)  2: input_zero_point (i32)
    // 3: weight_int8 (i32)  4: weight_scale (f32)  5: weight_zero_point (i32)
    // 6: bias_fp32 (f32)  7: output_scale (f32)  8: output_zero_point (i32)
    (void)in_sizes; (void)n_in; (void)out_size;

    // 524288 positions / 2 per thread / 256 threads = 1024 blocks (exact)
    conv_fused<<<1024, 256>>>((const int2*)d_in[0], (float2*)d_out,
                              (const int4*)d_in[3], (const float*)d_in[4],
                              (const int*)d_in[5], (const float*)d_in[6],
                              (const float*)d_in[1], (const float*)d_in[7],
                              (const int*)d_in[2], (const int*)d_in[8]);
}